// round 1
// baseline (speedup 1.0000x reference)
#include <cuda_runtime.h>

// Problem constants (fixed by the dataset)
//   B=8, N=4096, C=768, H=12, DH=64, 3C=2304
// Pipeline:
//   K1: qkv[b,n,0:2304] = x[b,n,:] @ w_qkv^T                (32768 x 2304 x 768 SGEMM)
//   K2: per (b,h): G[d,e] = sum_n q[n,d]*k[n,e]; norms; softmax(G/(|q||k|)*T + tem) -> attn
//   K3: M_b[cp, h*64+e] = sum_d w_proj[cp, h*64+d] * attn[b,h,d,e]
//   K4: out[b,n,cp] = sum_c v[b,n,c] * M_b[cp,c] + b_proj[cp]   (per-b 4096 x 768 x 768 SGEMM)
// (K3/K4 use associativity: (V @ A^T) @ Wp^T == V @ (Wp @ A)^T, fusing away the
//  [B,N,C] intermediate entirely.)

// ---------------- scratch (allocation-free: __device__ globals) ----------------
__device__ float g_qkv[75497472];        // 8*4096*2304  (302 MB)
__device__ float g_attn[8 * 12 * 64 * 64];
__device__ float g_M[8 * 768 * 768];

// ---------------- generic NT SGEMM body: C[m,n] = sum_k A[m,k]*B[n,k] ----------------
// Block tile 128x128, K-tile 8, 256 threads, 8x8 per-thread microtile.
// All dims are multiples of the tiles -> no bounds checks.
__device__ __forceinline__ void sgemm_nt_body(
    const float* __restrict__ A, int lda,
    const float* __restrict__ B, int ldb,
    float*       __restrict__ C, int ldc,
    const float* __restrict__ bias, int K)
{
    __shared__ float As[8][128];
    __shared__ float Bs[8][128];

    const int tid  = threadIdx.x;
    const int tx   = tid & 15;   // N direction (16)
    const int ty   = tid >> 4;   // M direction (16)
    const int rowA = blockIdx.y * 128;
    const int colB = blockIdx.x * 128;

    // cooperative tile loads: 128 rows x 8 k, one float4 per thread per operand
    const int lr = tid >> 1;          // 0..127
    const int lc = (tid & 1) * 4;     // 0 or 4
    const float* Ap = A + (long long)(rowA + lr) * lda + lc;
    const float* Bp = B + (long long)(colB + lr) * ldb + lc;

    float acc[8][8];
#pragma unroll
    for (int i = 0; i < 8; i++)
#pragma unroll
        for (int j = 0; j < 8; j++) acc[i][j] = 0.f;

    for (int k0 = 0; k0 < K; k0 += 8) {
        const float4 a4 = *(const float4*)(Ap + k0);
        const float4 b4 = *(const float4*)(Bp + k0);
        __syncthreads();   // previous iteration's reads done
        As[lc + 0][lr] = a4.x; As[lc + 1][lr] = a4.y;
        As[lc + 2][lr] = a4.z; As[lc + 3][lr] = a4.w;
        Bs[lc + 0][lr] = b4.x; Bs[lc + 1][lr] = b4.y;
        Bs[lc + 2][lr] = b4.z; Bs[lc + 3][lr] = b4.w;
        __syncthreads();
#pragma unroll
        for (int kk = 0; kk < 8; kk++) {
            float a[8], b[8];
            *(float4*)&a[0] = *(const float4*)&As[kk][ty * 8];
            *(float4*)&a[4] = *(const float4*)&As[kk][ty * 8 + 4];
            *(float4*)&b[0] = *(const float4*)&Bs[kk][tx * 8];
            *(float4*)&b[4] = *(const float4*)&Bs[kk][tx * 8 + 4];
#pragma unroll
            for (int i = 0; i < 8; i++)
#pragma unroll
                for (int j = 0; j < 8; j++)
                    acc[i][j] = fmaf(a[i], b[j], acc[i][j]);
        }
    }

    float bj[8];
#pragma unroll
    for (int j = 0; j < 8; j++) bj[j] = bias ? bias[colB + tx * 8 + j] : 0.f;

#pragma unroll
    for (int i = 0; i < 8; i++) {
        const long long row = rowA + ty * 8 + i;
        float* cp = C + row * (long long)ldc + colB + tx * 8;
        float4 v0 = make_float4(acc[i][0] + bj[0], acc[i][1] + bj[1],
                                acc[i][2] + bj[2], acc[i][3] + bj[3]);
        float4 v1 = make_float4(acc[i][4] + bj[4], acc[i][5] + bj[5],
                                acc[i][6] + bj[6], acc[i][7] + bj[7]);
        *(float4*)cp       = v0;
        *(float4*)(cp + 4) = v1;
    }
}

// K1: qkv = x @ w_qkv^T
__global__ __launch_bounds__(256, 2)
void k1_qkv(const float* __restrict__ x, const float* __restrict__ wqkv)
{
    sgemm_nt_body(x, 768, wqkv, 768, g_qkv, 2304, nullptr, 768);
}

// K4: out[b] = v[b] @ M_b^T + b_proj     (v[b] is the 3rd third of qkv rows)
__global__ __launch_bounds__(256, 2)
void k4_out(const float* __restrict__ bproj, float* __restrict__ out)
{
    const int z = blockIdx.z;
    const float* A = g_qkv + (long long)z * 4096 * 2304 + 1536;  // v slice, lda=2304
    const float* B = g_M   + (long long)z * 768 * 768;
    float*       C = out   + (long long)z * 4096 * 768;
    sgemm_nt_body(A, 2304, B, 768, C, 768, bproj, 768);
}

// ---------------- K2: gram + norms + softmax ----------------
// One block per (h, b). 256 threads as 16x16, 4x4 microtile over the 64x64 gram.
__global__ __launch_bounds__(256)
void k2_attn(const float* __restrict__ tem,
             const float* __restrict__ temperature,
             const int*   __restrict__ pos_flag)
{
    const int h = blockIdx.x;
    const int b = blockIdx.y;

    __shared__ float qs[32][64];
    __shared__ float ks[32][64];
    __shared__ float L[64 * 65];
    __shared__ float inq[64], ink[64];

    const int tid = threadIdx.x;
    const int tx = tid & 15;   // e direction
    const int ty = tid >> 4;   // d direction

    float acc[4][4] = {};
    float sqq[4] = {0.f, 0.f, 0.f, 0.f};
    float sqk[4] = {0.f, 0.f, 0.f, 0.f};

    const float* q0 = g_qkv + (long long)b * 4096 * 2304 + h * 64;
    const float* kp0 = q0 + 768;

    const int lr = tid >> 3;         // 0..31 (n within tile)
    const int lc = (tid & 7) * 4;    // 0..28

    for (int n0 = 0; n0 < 4096; n0 += 32) {
        const float* pq = q0  + (long long)(n0 + lr) * 2304;
        const float* pk = kp0 + (long long)(n0 + lr) * 2304;
        const float4 qa = *(const float4*)(pq + lc);
        const float4 qb = *(const float4*)(pq + lc + 32);
        const float4 ka = *(const float4*)(pk + lc);
        const float4 kb = *(const float4*)(pk + lc + 32);
        __syncthreads();
        *(float4*)&qs[lr][lc]      = qa;
        *(float4*)&qs[lr][lc + 32] = qb;
        *(float4*)&ks[lr][lc]      = ka;
        *(float4*)&ks[lr][lc + 32] = kb;
        __syncthreads();
#pragma unroll
        for (int kk = 0; kk < 32; kk++) {
            float qv[4], kv[4];
            *(float4*)qv = *(const float4*)&qs[kk][ty * 4];
            *(float4*)kv = *(const float4*)&ks[kk][tx * 4];
#pragma unroll
            for (int i = 0; i < 4; i++)
#pragma unroll
                for (int j = 0; j < 4; j++)
                    acc[i][j] = fmaf(qv[i], kv[j], acc[i][j]);
            if (tx == 0) {
#pragma unroll
                for (int i = 0; i < 4; i++) sqq[i] = fmaf(qv[i], qv[i], sqq[i]);
            }
            if (ty == 0) {
#pragma unroll
                for (int j = 0; j < 4; j++) sqk[j] = fmaf(kv[j], kv[j], sqk[j]);
            }
        }
    }

    if (tx == 0) {
#pragma unroll
        for (int i = 0; i < 4; i++)
            inq[ty * 4 + i] = 1.f / fmaxf(sqrtf(sqq[i]), 1e-12f);
    }
    if (ty == 0) {
#pragma unroll
        for (int j = 0; j < 4; j++)
            ink[tx * 4 + j] = 1.f / fmaxf(sqrtf(sqk[j]), 1e-12f);
    }
    __syncthreads();

    const float tmpr = temperature[h];
    const bool addt = (pos_flag[0] == 0);
#pragma unroll
    for (int i = 0; i < 4; i++) {
        const int d = ty * 4 + i;
#pragma unroll
        for (int j = 0; j < 4; j++) {
            const int e = tx * 4 + j;
            float v = acc[i][j] * inq[d] * ink[e] * tmpr;
            if (addt) v += tem[(h * 64 + d) * 64 + e];
            L[d * 65 + e] = v;
        }
    }
    __syncthreads();

    if (tid < 64) {
        const int d = tid;
        float m = -1e30f;
        for (int e = 0; e < 64; e++) m = fmaxf(m, L[d * 65 + e]);
        float s = 0.f;
        for (int e = 0; e < 64; e++) {
            const float ex = expf(L[d * 65 + e] - m);
            L[d * 65 + e] = ex;
            s += ex;
        }
        const float inv = 1.f / s;
        float* outp = g_attn + (((long long)(b * 12 + h)) * 64 + d) * 64;
        for (int e = 0; e < 64; e++) outp[e] = L[d * 65 + e] * inv;
    }
}

// ---------------- K3: M_b = w_proj @ blockdiag(attn_b) ----------------
// grid (cp=768, b=8), 768 threads: thread c=(h*64+e) computes one M element.
__global__ __launch_bounds__(768)
void k3_buildM(const float* __restrict__ wproj)
{
    const int cp = blockIdx.x;
    const int b  = blockIdx.y;
    const int c  = threadIdx.x;         // 0..767
    __shared__ float ws[768];
    ws[c] = wproj[cp * 768 + c];
    __syncthreads();

    const int h = c >> 6;
    const int e = c & 63;
    const float* ar = g_attn + (((long long)(b * 12 + h)) * 64) * 64 + e;  // stride 64 over d
    const float* wr = ws + h * 64;
    float acc = 0.f;
#pragma unroll
    for (int d = 0; d < 64; d++)
        acc = fmaf(wr[d], ar[(long long)d * 64], acc);
    g_M[((long long)b * 768 + cp) * 768 + c] = acc;
}

// ---------------- launch ----------------
extern "C" void kernel_launch(void* const* d_in, const int* in_sizes, int n_in,
                              void* d_out, int out_size)
{
    const float* x     = (const float*)d_in[0];   // [8,4096,768]
    const float* tem   = (const float*)d_in[1];   // [12,64,64]
    const float* temp  = (const float*)d_in[2];   // [12,1,1]
    const float* wqkv  = (const float*)d_in[3];   // [2304,768]
    const float* wproj = (const float*)d_in[4];   // [768,768]
    const float* bproj = (const float*)d_in[5];   // [768]
    const int*   pflag = (const int*)d_in[6];     // scalar
    float* out = (float*)d_out;                   // [8,4096,768]

    // K1: qkv GEMM  (M=32768, N=2304, K=768)
    k1_qkv<<<dim3(2304 / 128, 32768 / 128, 1), 256>>>(x, wqkv);
    // K2: gram + norm + softmax  (96 blocks)
    k2_attn<<<dim3(12, 8), 256>>>(tem, temp, pflag);
    // K3: fold attn into projection matrix
    k3_buildM<<<dim3(768, 8), 768>>>(wproj);
    // K4: final per-batch GEMM with bias  (M=4096, N=768, K=768, z=8)
    k4_out<<<dim3(768 / 128, 4096 / 128, 8), 256>>>(bproj, out);
}

// round 5
// speedup vs baseline: 2.8260x; 2.8260x over previous
#include <cuda_runtime.h>
#include <cuda_bf16.h>
#include <cstdint>

// B=8, N=4096, C=768, H=12, DH=64, 3C=2304
// compute_100 base target: tcgen05 unavailable -> legacy tensor path:
//   mma.sync.aligned.m16n8k16 bf16 (3-pass hi/lo split, fp32 accum)
//   ldmatrix + cp.async 2-stage pipeline.
//
// Pipeline:
//   conv : x, w_qkv -> bf16 hi/lo
//   K1   : qkv = x @ w_qkv^T (32768x2304x768). cols<1536 -> g_qk fp32; else v -> hi/lo bf16
//   K2a  : partial gram + sumsq over n-quarters (fp32)
//   K2b  : reduce + l2norm + tem + softmax
//   K3   : M_b = w_proj @ blockdiag(attn_b) -> bf16 hi/lo
//   K4   : out[b] = v[b] @ M_b^T + b_proj (8 x 4096x768x768)

// ---------------- device scratch ----------------
__device__ __align__(128) float          g_qk[32768u * 1536u];
__device__ __align__(128) __nv_bfloat16  g_vhi[32768u * 768u];
__device__ __align__(128) __nv_bfloat16  g_vlo[32768u * 768u];
__device__ __align__(128) __nv_bfloat16  g_xhi[32768u * 768u];
__device__ __align__(128) __nv_bfloat16  g_xlo[32768u * 768u];
__device__ __align__(128) __nv_bfloat16  g_whi[2304u * 768u];
__device__ __align__(128) __nv_bfloat16  g_wlo[2304u * 768u];
__device__ __align__(128) __nv_bfloat16  g_Mhi[8u * 768u * 768u];
__device__ __align__(128) __nv_bfloat16  g_Mlo[8u * 768u * 768u];
__device__ __align__(128) float          g_pG[96u * 4u * 4096u];
__device__ __align__(128) float          g_pq[96u * 4u * 64u];
__device__ __align__(128) float          g_pk[96u * 4u * 64u];
__device__ __align__(128) float          g_attn[96u * 4096u];

// ---------------- helpers ----------------
__device__ __forceinline__ uint32_t smem_u32(const void* p) {
    uint32_t a;
    asm("{ .reg .u64 t; cvta.to.shared.u64 t, %1; cvt.u32.u64 %0, t; }" : "=r"(a) : "l"(p));
    return a;
}
__device__ __forceinline__ void cp16(uint32_t dst, const void* src) {
    asm volatile("cp.async.ca.shared.global [%0], [%1], 16;" :: "r"(dst), "l"(src));
}
#define CP_COMMIT() asm volatile("cp.async.commit_group;")
#define CP_WAIT1()  asm volatile("cp.async.wait_group 1;")

__device__ __forceinline__ void ldm_x4(uint32_t* r, uint32_t addr) {
    asm volatile("ldmatrix.sync.aligned.m8n8.x4.shared.b16 {%0,%1,%2,%3}, [%4];"
                 : "=r"(r[0]), "=r"(r[1]), "=r"(r[2]), "=r"(r[3]) : "r"(addr));
}
__device__ __forceinline__ void mma16816(float* c, const uint32_t* a, const uint32_t* b) {
    asm volatile("mma.sync.aligned.m16n8k16.row.col.f32.bf16.bf16.f32 "
                 "{%0,%1,%2,%3}, {%4,%5,%6,%7}, {%8,%9}, {%0,%1,%2,%3};"
                 : "+f"(c[0]), "+f"(c[1]), "+f"(c[2]), "+f"(c[3])
                 : "r"(a[0]), "r"(a[1]), "r"(a[2]), "r"(a[3]), "r"(b[0]), "r"(b[1]));
}
__device__ __forceinline__ void split2(float x, __nv_bfloat16& h, __nv_bfloat16& l) {
    h = __float2bfloat16_rn(x);
    l = __float2bfloat16_rn(x - __bfloat162float(h));
}
__device__ __forceinline__ uint32_t pack2(__nv_bfloat16 a, __nv_bfloat16 b) {
    return (uint32_t)__bfloat16_as_ushort(a) | ((uint32_t)__bfloat16_as_ushort(b) << 16);
}

// ---------------- conv: fp32 -> bf16 hi/lo ----------------
__global__ void conv_split(const float4* __restrict__ src,
                           __nv_bfloat16* __restrict__ hi,
                           __nv_bfloat16* __restrict__ lo, int n4)
{
    for (int i = blockIdx.x * blockDim.x + threadIdx.x; i < n4; i += gridDim.x * blockDim.x) {
        float4 v = src[i];
        __align__(8) __nv_bfloat16 h[4], l[4];
        split2(v.x, h[0], l[0]); split2(v.y, h[1], l[1]);
        split2(v.z, h[2], l[2]); split2(v.w, h[3], l[3]);
        *(uint2*)(hi + 4 * i) = *(uint2*)h;
        *(uint2*)(lo + 4 * i) = *(uint2*)l;
    }
}

// ---------------- HMMA split-bf16 GEMM: C[m,n] = sum_k A[m,k] B[n,k] ----------------
// CTA 128x128x32 (2-stage cp.async), 8 warps as 4(M)x2(N), warp tile 32x64.
// Smem tile rows padded to 80B -> ldmatrix conflict-free (5r mod 8 is a permutation).
static constexpr int RS = 80;                       // bytes per smem row (64 data + 16 pad)
static constexpr int TILE_B = 128 * RS;             // 10240
static constexpr int STAGE_B = 4 * TILE_B;          // 40960 (Ahi,Alo,Bhi,Blo)
static constexpr int SMEM_BYTES = 2 * STAGE_B;      // 81920

template <int MODE>
__global__ __launch_bounds__(256, 2)
void mma_gemm(const float* __restrict__ bias, float* __restrict__ out)
{
    extern __shared__ __align__(128) char smem[];
    const uint32_t sb = smem_u32(smem);
    const int tid  = threadIdx.x;
    const int wid  = tid >> 5;
    const int lane = tid & 31;
    const int wm = wid & 3;          // 4 warps along M (32 rows each)
    const int wn = wid >> 2;         // 2 warps along N (64 cols each)

    const int c0   = blockIdx.x * 128;
    const int row0 = blockIdx.y * 128;

    const __nv_bfloat16 *Ahi, *Alo, *Bhi, *Blo;
    long long orow;
    if (MODE == 0) {
        Ahi = g_xhi + (long long)row0 * 768;  Alo = g_xlo + (long long)row0 * 768;
        Bhi = g_whi + (long long)c0 * 768;    Blo = g_wlo + (long long)c0 * 768;
        orow = row0;
    } else {
        const int b = blockIdx.z;
        const long long ab = ((long long)b * 4096 + row0) * 768;
        const long long bb = ((long long)b * 768 + c0) * 768;
        Ahi = g_vhi + ab;  Alo = g_vlo + ab;
        Bhi = g_Mhi + bb;  Blo = g_Mlo + bb;
        orow = (long long)b * 4096 + row0;
    }

    // per-thread cp.async geometry: per tile 512 chunks of 16B; 2 per thread
    // idx = it*256+tid: row = idx>>2 (0..127), ch = idx&3
    const int r0i = tid >> 2,  ch0 = (tid & 3);
    const int r1i = (256 + tid) >> 2, ch1 = (tid & 3);     // rows 64..127 same ch
    auto load_stage = [&](int buf, int k0) {
        const uint32_t stb = sb + buf * STAGE_B;
        const __nv_bfloat16* srcA[2] = {Ahi, Alo};
        const __nv_bfloat16* srcB[2] = {Bhi, Blo};
#pragma unroll
        for (int p = 0; p < 2; p++) {
            const uint32_t tA = stb + p * TILE_B;
            cp16(tA + r0i * RS + ch0 * 16, srcA[p] + (long long)r0i * 768 + k0 + ch0 * 8);
            cp16(tA + r1i * RS + ch1 * 16, srcA[p] + (long long)r1i * 768 + k0 + ch1 * 8);
            const uint32_t tB = stb + (2 + p) * TILE_B;
            cp16(tB + r0i * RS + ch0 * 16, srcB[p] + (long long)r0i * 768 + k0 + ch0 * 8);
            cp16(tB + r1i * RS + ch1 * 16, srcB[p] + (long long)r1i * 768 + k0 + ch1 * 8);
        }
    };

    float C[64];
#pragma unroll
    for (int i = 0; i < 64; i++) C[i] = 0.f;

    // ldmatrix address components
    const int arow = lane & 15;              // m row within 16
    const int aksel = (lane >> 4) * 16;      // bytes: k half (8 bf16)
    const int brow = (lane & 7) | ((lane >> 4) << 3);   // n row within 16
    const int bko  = ((lane >> 3) & 1) * 16; // bytes

    // prologue
    load_stage(0, 0); CP_COMMIT();
    load_stage(1, 32); CP_COMMIT();

    const int T = 24;   // 768 / 32
    for (int t = 0; t < T; t++) {
        CP_WAIT1();
        __syncthreads();
        const uint32_t stb = sb + (t & 1) * STAGE_B;
        const uint32_t sAhi = stb, sAlo = stb + TILE_B;
        const uint32_t sBhi = stb + 2 * TILE_B, sBlo = stb + 3 * TILE_B;
#pragma unroll
        for (int kk = 0; kk < 2; kk++) {
            const int kb = kk * 32;    // byte offset of k16 block
            uint32_t a_hi[2][4], a_lo[2][4];
#pragma unroll
            for (int mi = 0; mi < 2; mi++) {
                const uint32_t ro = (uint32_t)(wm * 32 + mi * 16 + arow) * RS + kb + aksel;
                ldm_x4(a_hi[mi], sAhi + ro);
                ldm_x4(a_lo[mi], sAlo + ro);
            }
#pragma unroll
            for (int g = 0; g < 4; g++) {       // n16 groups
                uint32_t b_hi[4], b_lo[4];
                const uint32_t ro = (uint32_t)(wn * 64 + g * 16 + brow) * RS + kb + bko;
                ldm_x4(b_hi, sBhi + ro);
                ldm_x4(b_lo, sBlo + ro);
#pragma unroll
                for (int mi = 0; mi < 2; mi++) {
#pragma unroll
                    for (int j = 0; j < 2; j++) {
                        float* c = C + (mi * 8 + g * 2 + j) * 4;
                        mma16816(c, a_hi[mi], b_hi + 2 * j);
                        mma16816(c, a_hi[mi], b_lo + 2 * j);
                        mma16816(c, a_lo[mi], b_hi + 2 * j);
                    }
                }
            }
        }
        __syncthreads();
        if (t + 2 < T) load_stage(t & 1, (t + 2) * 32);
        CP_COMMIT();
    }

    // ---------------- epilogue ----------------
    const int crow = lane >> 2;               // 0..7
    const int ccol = (lane & 3) * 2;          // even col within n8
#pragma unroll
    for (int mi = 0; mi < 2; mi++) {
#pragma unroll
        for (int n8 = 0; n8 < 8; n8++) {
            const float* c = C + (mi * 8 + n8) * 4;
            const int col = c0 + wn * 64 + n8 * 8 + ccol;
            const long long r0g = orow + wm * 32 + mi * 16 + crow;
            const long long r1g = r0g + 8;
            if (MODE == 0) {
                if (c0 < 1536) {
                    float2 v0 = make_float2(c[0], c[1]);
                    float2 v1 = make_float2(c[2], c[3]);
                    *(float2*)(g_qk + r0g * 1536 + col) = v0;
                    *(float2*)(g_qk + r1g * 1536 + col) = v1;
                } else {
                    const int vc = col - 1536;
                    __nv_bfloat16 h0, l0, h1, l1;
                    split2(c[0], h0, l0); split2(c[1], h1, l1);
                    *(uint32_t*)(g_vhi + r0g * 768 + vc) = pack2(h0, h1);
                    *(uint32_t*)(g_vlo + r0g * 768 + vc) = pack2(l0, l1);
                    split2(c[2], h0, l0); split2(c[3], h1, l1);
                    *(uint32_t*)(g_vhi + r1g * 768 + vc) = pack2(h0, h1);
                    *(uint32_t*)(g_vlo + r1g * 768 + vc) = pack2(l0, l1);
                }
            } else {
                const float b0 = bias[col], b1 = bias[col + 1];
                *(float2*)(out + r0g * 768 + col) = make_float2(c[0] + b0, c[1] + b1);
                *(float2*)(out + r1g * 768 + col) = make_float2(c[2] + b0, c[3] + b1);
            }
        }
    }
}

// ---------------- K2a: partial gram + sumsq over n-quarters ----------------
__global__ __launch_bounds__(256)
void k2a(void)
{
    const int h = blockIdx.x, b = blockIdx.y, s = blockIdx.z;
    const int bh = b * 12 + h;

    __shared__ float qs[32][64];
    __shared__ float ks[32][64];

    const int tid = threadIdx.x;
    const int tx = tid & 15;
    const int ty = tid >> 4;

    float acc[4][4] = {};
    float sqq[4] = {0.f, 0.f, 0.f, 0.f};
    float sqk[4] = {0.f, 0.f, 0.f, 0.f};

    const float* q0 = g_qk + (size_t)b * 4096 * 1536 + h * 64;
    const float* k0 = q0 + 768;

    const int lr = tid >> 3;
    const int lc = (tid & 7) * 4;

    const int nbeg = s * 1024;
    for (int n0 = nbeg; n0 < nbeg + 1024; n0 += 32) {
        const float* pq = q0 + (size_t)(n0 + lr) * 1536;
        const float* pk = k0 + (size_t)(n0 + lr) * 1536;
        const float4 qa = *(const float4*)(pq + lc);
        const float4 qb = *(const float4*)(pq + lc + 32);
        const float4 ka = *(const float4*)(pk + lc);
        const float4 kb = *(const float4*)(pk + lc + 32);
        __syncthreads();
        *(float4*)&qs[lr][lc]      = qa;
        *(float4*)&qs[lr][lc + 32] = qb;
        *(float4*)&ks[lr][lc]      = ka;
        *(float4*)&ks[lr][lc + 32] = kb;
        __syncthreads();
#pragma unroll
        for (int kk = 0; kk < 32; kk++) {
            float qv[4], kv[4];
            *(float4*)qv = *(const float4*)&qs[kk][ty * 4];
            *(float4*)kv = *(const float4*)&ks[kk][tx * 4];
#pragma unroll
            for (int i = 0; i < 4; i++)
#pragma unroll
                for (int j = 0; j < 4; j++)
                    acc[i][j] = fmaf(qv[i], kv[j], acc[i][j]);
            if (tx == 0) {
#pragma unroll
                for (int i = 0; i < 4; i++) sqq[i] = fmaf(qv[i], qv[i], sqq[i]);
            }
            if (ty == 0) {
#pragma unroll
                for (int j = 0; j < 4; j++) sqk[j] = fmaf(kv[j], kv[j], sqk[j]);
            }
        }
    }

    float* gb = g_pG + ((size_t)bh * 4 + s) * 4096;
#pragma unroll
    for (int i = 0; i < 4; i++)
#pragma unroll
        for (int j = 0; j < 4; j++)
            gb[(ty * 4 + i) * 64 + tx * 4 + j] = acc[i][j];
    if (tx == 0) {
#pragma unroll
        for (int i = 0; i < 4; i++) g_pq[((size_t)bh * 4 + s) * 64 + ty * 4 + i] = sqq[i];
    }
    if (ty == 0) {
#pragma unroll
        for (int j = 0; j < 4; j++) g_pk[((size_t)bh * 4 + s) * 64 + tx * 4 + j] = sqk[j];
    }
}

// ---------------- K2b: reduce + norm + softmax ----------------
__global__ __launch_bounds__(256)
void k2b(const float* __restrict__ tem,
         const float* __restrict__ temperature,
         const int* __restrict__ pos_flag)
{
    const int h = blockIdx.x, b = blockIdx.y;
    const int bh = b * 12 + h;
    const int tid = threadIdx.x;

    __shared__ float L[64 * 65];
    __shared__ float inq[64], ink[64];

#pragma unroll
    for (int i = 0; i < 16; i++) {
        const int idx = i * 256 + tid;
        float g = 0.f;
#pragma unroll
        for (int s = 0; s < 4; s++) g += g_pG[((size_t)bh * 4 + s) * 4096 + idx];
        L[(idx >> 6) * 65 + (idx & 63)] = g;
    }
    if (tid < 64) {
        float sq = 0.f;
#pragma unroll
        for (int s = 0; s < 4; s++) sq += g_pq[((size_t)bh * 4 + s) * 64 + tid];
        inq[tid] = 1.f / fmaxf(sqrtf(sq), 1e-12f);
    } else if (tid < 128) {
        const int e = tid - 64;
        float sk = 0.f;
#pragma unroll
        for (int s = 0; s < 4; s++) sk += g_pk[((size_t)bh * 4 + s) * 64 + e];
        ink[e] = 1.f / fmaxf(sqrtf(sk), 1e-12f);
    }
    __syncthreads();

    if (tid < 64) {
        const int d = tid;
        const float tmpr = temperature[h];
        const bool addt = (pos_flag[0] == 0);
        const float iq = inq[d];
        float m = -1e30f;
        for (int e = 0; e < 64; e++) {
            float v = L[d * 65 + e] * iq * ink[e] * tmpr;
            if (addt) v += tem[(h * 64 + d) * 64 + e];
            L[d * 65 + e] = v;
            m = fmaxf(m, v);
        }
        float ssum = 0.f;
        for (int e = 0; e < 64; e++) {
            const float ex = expf(L[d * 65 + e] - m);
            L[d * 65 + e] = ex;
            ssum += ex;
        }
        const float inv = 1.f / ssum;
        float* outp = g_attn + (size_t)bh * 4096 + d * 64;
        for (int e = 0; e < 64; e++) outp[e] = L[d * 65 + e] * inv;
    }
}

// ---------------- K3: M_b = w_proj @ blockdiag(attn_b) -> bf16 hi/lo ----------------
__global__ __launch_bounds__(768)
void k3_buildM(const float* __restrict__ wproj)
{
    const int cp = blockIdx.x;
    const int b  = blockIdx.y;
    const int c  = threadIdx.x;
    __shared__ float ws[768];
    ws[c] = wproj[cp * 768 + c];
    __syncthreads();

    const int h = c >> 6;
    const int e = c & 63;
    const float* ar = g_attn + ((size_t)(b * 12 + h)) * 4096 + e;
    const float* wr = ws + h * 64;
    float acc = 0.f;
#pragma unroll
    for (int d = 0; d < 64; d++)
        acc = fmaf(wr[d], ar[(size_t)d * 64], acc);
    __nv_bfloat16 hi, lo;
    split2(acc, hi, lo);
    const size_t o = ((size_t)b * 768 + cp) * 768 + c;
    g_Mhi[o] = hi;
    g_Mlo[o] = lo;
}

// ---------------- launch ----------------
extern "C" void kernel_launch(void* const* d_in, const int* in_sizes, int n_in,
                              void* d_out, int out_size)
{
    const float* x     = (const float*)d_in[0];
    const float* tem   = (const float*)d_in[1];
    const float* temp  = (const float*)d_in[2];
    const float* wqkv  = (const float*)d_in[3];
    const float* wproj = (const float*)d_in[4];
    const float* bproj = (const float*)d_in[5];
    const int*   pflag = (const int*)d_in[6];
    float* out = (float*)d_out;

    cudaFuncSetAttribute(mma_gemm<0>, cudaFuncAttributeMaxDynamicSharedMemorySize, SMEM_BYTES);
    cudaFuncSetAttribute(mma_gemm<1>, cudaFuncAttributeMaxDynamicSharedMemorySize, SMEM_BYTES);

    __nv_bfloat16 *xhi, *xlo, *whi, *wlo;
    cudaGetSymbolAddress((void**)&xhi, g_xhi);
    cudaGetSymbolAddress((void**)&xlo, g_xlo);
    cudaGetSymbolAddress((void**)&whi, g_whi);
    cudaGetSymbolAddress((void**)&wlo, g_wlo);

    conv_split<<<1024, 256>>>((const float4*)x, xhi, xlo, 25165824 / 4);
    conv_split<<<256, 256>>>((const float4*)wqkv, whi, wlo, 1769472 / 4);

    // K1: 32768 x 2304 x 768
    mma_gemm<0><<<dim3(18, 256, 1), 256, SMEM_BYTES>>>(nullptr, nullptr);
    // K2: gram + softmax
    k2a<<<dim3(12, 8, 4), 256>>>();
    k2b<<<dim3(12, 8), 256>>>(tem, temp, pflag);
    // K3
    k3_buildM<<<dim3(768, 8), 768>>>(wproj);
    // K4: 8 x (4096 x 768 x 768) + bias
    mma_gemm<1><<<dim3(6, 32, 8), 256, SMEM_BYTES>>>(bproj, out);
}